// round 15
// baseline (speedup 1.0000x reference)
#include <cuda_runtime.h>
#include <cuda_fp16.h>
#include <cstdint>

#define NN 50000
#define EE 800000
#define GG 500
#define LL 3
#define NB1 ((NN + 1023) / 1024)

// ---------------- mma.sync helpers (baseline PTX, no sm_103a features) ----------------
__device__ __forceinline__ uint32_t smem_u32(const void* p) {
    uint32_t a;
    asm("{ .reg .u64 t; cvta.to.shared.u64 t, %1; cvt.u32.u64 %0, t; }" : "=r"(a) : "l"(p));
    return a;
}
__device__ __forceinline__ void ldsm4(uint32_t& r0, uint32_t& r1, uint32_t& r2, uint32_t& r3,
                                      uint32_t addr) {
    asm volatile("ldmatrix.sync.aligned.m8n8.x4.shared.b16 {%0,%1,%2,%3}, [%4];"
                 : "=r"(r0), "=r"(r1), "=r"(r2), "=r"(r3) : "r"(addr));
}
__device__ __forceinline__ void mma16816(float* c, uint32_t a0, uint32_t a1, uint32_t a2,
                                         uint32_t a3, uint32_t b0, uint32_t b1) {
    asm volatile("mma.sync.aligned.m16n8k16.row.col.f32.f16.f16.f32 "
                 "{%0,%1,%2,%3}, {%4,%5,%6,%7}, {%8,%9}, {%0,%1,%2,%3};"
                 : "+f"(c[0]), "+f"(c[1]), "+f"(c[2]), "+f"(c[3])
                 : "r"(a0), "r"(a1), "r"(a2), "r"(a3), "r"(b0), "r"(b1));
}

// ---------------- scratch (static device globals; no allocation) ----------------
__device__ int    g_is64;
__device__ int    g_degi[NN];
__device__ float  g_degf[NN];
__device__ float  g_dinv[NN];
__device__ int    g_ptr[NN + 1];
__device__ int    g_cnt[NN];
__device__ int    g_tick;
__device__ int    g_base;
__device__ int    g_csrc[EE];
__device__ float  g_cw[EE];
__device__ __half g_xc[NN * 128];    // [x | s] concat fp16, row stride 128
__device__ __half g_y16[NN * 64];    // xc @ W1 fp16
__device__ __half g_hs16[NN * 64];   // s @ gcnW fp16
__device__ __half g_z16[NN * 64];    // relu(agg(y)+b1) fp16
__device__ __half g_w16[79872];      // weights fp16, [n][k] layouts

// weight buffer offsets (halves)
#define W_DUAL  0       // 3 x [128n][128k]  (n<64: ginW1; n>=64: gcn on k>=64, 0 else)
#define W_GIN2  49152   // 3 x [64][64]
#define W_PREMB 61440   // [128n][144k] (n<64: pre on k<128; n>=64: emb on k>=128; 0 else)
#define W_TOTAL 79872

// ---------------- index loading: int64 vs int32 auto-detect ----------------
__device__ __forceinline__ int ld_idx(const void* p, long i) {
    if (g_is64) return (int)((const long long*)p)[i];
    return ((const int*)p)[i];
}

// ---------------- init: zero counters + scan state + dtype detect ----------------
__global__ void init_k(const int* w) {
    int i = blockIdx.x * blockDim.x + threadIdx.x;
    if (i < NN) g_degi[i] = 0;
    else if (i < 2 * NN) g_cnt[i - NN] = 0;
    if (i == 0) {
        g_tick = 0;
        g_base = 0;
        int nz = 0;
#pragma unroll
        for (int j = 0; j < 8; j++)
            if (w[2 * j + 1] != 0) nz++;
        g_is64 = (nz == 0) ? 1 : 0;
    }
}

// ---------------- weight convert + transpose to fp16 ----------------
__global__ void convw_k(const float* __restrict__ gin1, const float* __restrict__ gcn,
                        const float* __restrict__ gin2, const float* __restrict__ pre,
                        const float* __restrict__ emb) {
    int idx = blockIdx.x * blockDim.x + threadIdx.x;
    if (idx >= W_TOTAL) return;
    float v;
    if (idx < 49152) {            // dual: [l][n=128][k=128]
        int l = idx / 16384, r = idx % 16384, n = r / 128, k = r % 128;
        if (n < 64) v = gin1[l * 8192 + k * 64 + n];
        else if (k >= 64) v = gcn[l * 4096 + (k - 64) * 64 + (n - 64)];
        else v = 0.f;
    } else if (idx < 61440) {     // ginW2 [l][64][64]
        int r0 = idx - 49152; int l = r0 / 4096, r = r0 % 4096, n = r / 64, k = r % 64;
        v = gin2[l * 4096 + k * 64 + n];
    } else {                      // premb: [n=128][k=144]
        int r = idx - W_PREMB; int n = r / 144, k = r % 144;
        if (n < 64) v = (k < 128) ? pre[k * 64 + n] : 0.f;
        else v = (k >= 128) ? emb[(k - 128) * 64 + (n - 64)] : 0.f;
    }
    g_w16[idx] = __float2half_rn(v);
}

// ---------------- degree histogram ----------------
__global__ void hist_k(const void* ei) {
    int e = blockIdx.x * blockDim.x + threadIdx.x;
    if (e < EE) {
        int d = ld_idx(ei, (long)EE + e);
        atomicAdd(&g_degi[d], 1);
    }
}

// ---------------- single-pass chained scan (deg/dinv fused) ----------------
// 49 blocks x 1024: all co-resident -> serialized block-offset handoff is safe.
__global__ void scan_k() {
    __shared__ int wsum[32];
    __shared__ int s_off;
    int tid = threadIdx.x, b = blockIdx.x;
    int lane = tid & 31, wid = tid >> 5;
    int i = b * 1024 + tid;
    int v = (i < NN) ? g_degi[i] : 0;
    if (i < NN) {
        float d = (float)(v + 1);
        g_degf[i] = d;
        g_dinv[i] = rsqrtf(d);
    }
    // warp-shuffle inclusive scan
    int x = v;
#pragma unroll
    for (int d = 1; d < 32; d <<= 1) {
        int t = __shfl_up_sync(0xFFFFFFFFu, x, d);
        if (lane >= d) x += t;
    }
    if (lane == 31) wsum[wid] = x;
    __syncthreads();
    if (wid == 0) {
        int y = wsum[lane];
#pragma unroll
        for (int d = 1; d < 32; d <<= 1) {
            int t = __shfl_up_sync(0xFFFFFFFFu, y, d);
            if (lane >= d) y += t;
        }
        wsum[lane] = y;
    }
    __syncthreads();
    int incl = x + (wid > 0 ? wsum[wid - 1] : 0);
    // chained block-offset handoff
    if (tid == 1023) {
        while (atomicAdd(&g_tick, 0) != b) {}
        s_off = atomicAdd(&g_base, incl);
        __threadfence();
        atomicExch(&g_tick, b + 1);
    }
    __syncthreads();
    if (i < NN) g_ptr[i] = s_off + incl - v;
    if (b == NB1 - 1 && tid == 1023) g_ptr[NN] = s_off + incl;
}

// ---------------- CSR fill ----------------
__global__ void fill_k(const void* ei) {
    int e = blockIdx.x * blockDim.x + threadIdx.x;
    if (e < EE) {
        int sn = ld_idx(ei, e);
        int dn = ld_idx(ei, (long)EE + e);
        int pos = g_ptr[dn] + atomicAdd(&g_cnt[dn], 1);
        g_csrc[pos] = sn;
        g_cw[pos] = g_dinv[sn] * g_dinv[dn];
    }
}

// ---------------- fused GIN(y) + GCN(hs) aggregation, fp16 gathers, 4-edge ILP ----------------
__global__ void agg_fused_k(const float* __restrict__ b1, const float* __restrict__ bg) {
    int nd = (blockIdx.x * blockDim.x + threadIdx.x) >> 5;
    if (nd >= NN) return;
    int lane = threadIdx.x & 31;
    int l4 = lane & 15;
    bool isY = lane < 16;
    const uint2* base = isY ? (const uint2*)g_y16 : (const uint2*)g_hs16;
    int b = g_ptr[nd], e = g_ptr[nd + 1];
    float4 a0 = make_float4(0.f, 0.f, 0.f, 0.f);
    float4 a1 = make_float4(0.f, 0.f, 0.f, 0.f);
    float4 a2 = make_float4(0.f, 0.f, 0.f, 0.f);
    float4 a3 = make_float4(0.f, 0.f, 0.f, 0.f);
    int i = b;
    for (; i + 3 < e; i += 4) {
        int s0 = g_csrc[i], s1 = g_csrc[i + 1], s2 = g_csrc[i + 2], s3 = g_csrc[i + 3];
        float w0 = isY ? 1.f : g_cw[i];
        float w1 = isY ? 1.f : g_cw[i + 1];
        float w2 = isY ? 1.f : g_cw[i + 2];
        float w3 = isY ? 1.f : g_cw[i + 3];
        uint2 u0 = base[(long)s0 * 16 + l4];
        uint2 u1 = base[(long)s1 * 16 + l4];
        uint2 u2 = base[(long)s2 * 16 + l4];
        uint2 u3 = base[(long)s3 * 16 + l4];
        float2 p0 = __half22float2(*(const __half2*)&u0.x);
        float2 p1 = __half22float2(*(const __half2*)&u0.y);
        a0.x = fmaf(w0, p0.x, a0.x); a0.y = fmaf(w0, p0.y, a0.y);
        a0.z = fmaf(w0, p1.x, a0.z); a0.w = fmaf(w0, p1.y, a0.w);
        float2 q0 = __half22float2(*(const __half2*)&u1.x);
        float2 q1 = __half22float2(*(const __half2*)&u1.y);
        a1.x = fmaf(w1, q0.x, a1.x); a1.y = fmaf(w1, q0.y, a1.y);
        a1.z = fmaf(w1, q1.x, a1.z); a1.w = fmaf(w1, q1.y, a1.w);
        float2 r0 = __half22float2(*(const __half2*)&u2.x);
        float2 r1 = __half22float2(*(const __half2*)&u2.y);
        a2.x = fmaf(w2, r0.x, a2.x); a2.y = fmaf(w2, r0.y, a2.y);
        a2.z = fmaf(w2, r1.x, a2.z); a2.w = fmaf(w2, r1.y, a2.w);
        float2 t0 = __half22float2(*(const __half2*)&u3.x);
        float2 t1 = __half22float2(*(const __half2*)&u3.y);
        a3.x = fmaf(w3, t0.x, a3.x); a3.y = fmaf(w3, t0.y, a3.y);
        a3.z = fmaf(w3, t1.x, a3.z); a3.w = fmaf(w3, t1.y, a3.w);
    }
    for (; i < e; i++) {
        int s0 = g_csrc[i];
        float w0 = isY ? 1.f : g_cw[i];
        uint2 u0 = base[(long)s0 * 16 + l4];
        float2 p0 = __half22float2(*(const __half2*)&u0.x);
        float2 p1 = __half22float2(*(const __half2*)&u0.y);
        a0.x = fmaf(w0, p0.x, a0.x); a0.y = fmaf(w0, p0.y, a0.y);
        a0.z = fmaf(w0, p1.x, a0.z); a0.w = fmaf(w0, p1.y, a0.w);
    }
    a0.x += a1.x + a2.x + a3.x;
    a0.y += a1.y + a2.y + a3.y;
    a0.z += a1.z + a2.z + a3.z;
    a0.w += a1.w + a2.w + a3.w;
    float ws = isY ? 1.f : (1.f / g_degf[nd]);
    {
        uint2 us = base[(long)nd * 16 + l4];
        float2 p0 = __half22float2(*(const __half2*)&us.x);
        float2 p1 = __half22float2(*(const __half2*)&us.y);
        a0.x = fmaf(ws, p0.x, a0.x); a0.y = fmaf(ws, p0.y, a0.y);
        a0.z = fmaf(ws, p1.x, a0.z); a0.w = fmaf(ws, p1.y, a0.w);
    }
    if (isY) {
        float r0 = fmaxf(a0.x + b1[4 * l4 + 0], 0.f);
        float r1 = fmaxf(a0.y + b1[4 * l4 + 1], 0.f);
        float r2 = fmaxf(a0.z + b1[4 * l4 + 2], 0.f);
        float r3 = fmaxf(a0.w + b1[4 * l4 + 3], 0.f);
        __half2 h01 = __floats2half2_rn(r0, r1);
        __half2 h23 = __floats2half2_rn(r2, r3);
        uint2 pk; pk.x = *(const unsigned*)&h01; pk.y = *(const unsigned*)&h23;
        ((uint2*)g_z16)[(long)nd * 16 + l4] = pk;
    } else {
        float r0 = tanhf(a0.x + bg[4 * l4 + 0]);
        float r1 = tanhf(a0.y + bg[4 * l4 + 1]);
        float r2 = tanhf(a0.z + bg[4 * l4 + 2]);
        float r3 = tanhf(a0.w + bg[4 * l4 + 3]);
        __half2 h01 = __floats2half2_rn(r0, r1);
        __half2 h23 = __floats2half2_rn(r2, r3);
        uint2 pk; pk.x = *(const unsigned*)&h01; pk.y = *(const unsigned*)&h23;
        ((uint2*)g_xc)[(long)nd * 32 + 16 + l4] = pk;
    }
}

// ---------------- HMMA GEMM ----------------
// F32IN: 0 = fp16 single input; 2 = fp32 concat (cols<128 from in/ldin, rest from in2/ldin2).
// NOUT=128 splits outputs: cols<64 -> outA (+biasA), cols>=64 -> outB (+biasB).
template <int K, int NOUT, int ACT, int HOUT, int F32IN>
__global__ void __launch_bounds__(256) hgemm_k(
        const void* __restrict__ in, int ldin,
        const void* __restrict__ in2, int ldin2,
        const __half* __restrict__ wt,
        const float* __restrict__ biasA, const float* __restrict__ biasB, int n,
        void* __restrict__ outA, int ldA, void* __restrict__ outB, int ldB) {
    constexpr int KP = K + 8;
    constexpr int KQ = K / 4;
    extern __shared__ __half dsm[];
    __half* sA = dsm;                     // [128][KP]
    __half* sB = dsm + 128 * KP;          // [NOUT][KP]

    int tid = threadIdx.x;
    int w = tid >> 5, lane = tid & 31;
    int rowBase = blockIdx.x * 128;

    for (int idx = tid; idx < 128 * KQ; idx += 256) {
        int r = idx / KQ, q = idx - r * KQ;
        int gr = rowBase + r;
        uint2 pk = make_uint2(0u, 0u);
        if (gr < n) {
            if (F32IN == 2) {
                int col = 4 * q;
                const float* src = (col < 128) ? &((const float*)in)[(long)gr * ldin + col]
                                               : &((const float*)in2)[(long)gr * ldin2 + (col - 128)];
                float4 v = *(const float4*)src;
                __half2 h0 = __floats2half2_rn(v.x, v.y);
                __half2 h1 = __floats2half2_rn(v.z, v.w);
                pk.x = *(const unsigned*)&h0;
                pk.y = *(const unsigned*)&h1;
            } else {
                pk = *(const uint2*)&((const __half*)in)[(long)gr * ldin + 4 * q];
            }
        }
        *(uint2*)&sA[r * KP + 4 * q] = pk;
    }
    for (int idx = tid; idx < NOUT * KQ; idx += 256) {
        int r = idx / KQ, q = idx - r * KQ;
        *(uint2*)&sB[r * KP + 4 * q] = *(const uint2*)&wt[(long)r * K + 4 * q];
    }
    __syncthreads();

    constexpr int NT = NOUT / 8;
    float acc[NT][4];
#pragma unroll
    for (int t = 0; t < NT; t++)
#pragma unroll
        for (int j = 0; j < 4; j++) acc[t][j] = 0.f;

    uint32_t aAddr = smem_u32(&sA[(16 * w + (lane & 15)) * KP + ((lane >> 4) << 3)]);
    int bRow = (lane & 7) + ((lane >> 4) << 3);
    int bCol = ((lane >> 3) & 1) << 3;
    uint32_t bAddr0 = smem_u32(&sB[bRow * KP + bCol]);

#pragma unroll
    for (int kk = 0; kk < K / 16; kk++) {
        uint32_t a0, a1, a2, a3;
        ldsm4(a0, a1, a2, a3, aAddr + kk * 32);
#pragma unroll
        for (int ntp = 0; ntp < NT / 2; ntp++) {
            uint32_t b0, b1, b2, b3;
            ldsm4(b0, b1, b2, b3, bAddr0 + (ntp * 16 * KP + kk * 16) * 2);
            mma16816(acc[2 * ntp],     a0, a1, a2, a3, b0, b1);
            mma16816(acc[2 * ntp + 1], a0, a1, a2, a3, b2, b3);
        }
    }

    int r0 = rowBase + 16 * w + (lane >> 2);
    int cb = (lane & 3) * 2;
#pragma unroll
    for (int nt = 0; nt < NT; nt++) {
        int c = nt * 8 + cb;
        float v00 = acc[nt][0], v01 = acc[nt][1], v10 = acc[nt][2], v11 = acc[nt][3];
        const float* bp = (NOUT == 128 && c >= 64) ? biasB : biasA;
        int cc = (NOUT == 128 && c >= 64) ? c - 64 : c;
        if (bp) {
            float bc0 = bp[cc], bc1 = bp[cc + 1];
            v00 += bc0; v01 += bc1; v10 += bc0; v11 += bc1;
        }
        if (ACT) {
            v00 = fmaxf(v00, 0.f); v01 = fmaxf(v01, 0.f);
            v10 = fmaxf(v10, 0.f); v11 = fmaxf(v11, 0.f);
        }
        void* op = outA;
        int ld = ldA;
        if (NOUT == 128 && c >= 64) { op = outB; ld = ldB; }
        if (HOUT) {
            __half* o = (__half*)op;
            if (r0 < n) {
                __half2 h = __floats2half2_rn(v00, v01);
                *(__half2*)&o[(long)r0 * ld + cc] = h;
            }
            if (r0 + 8 < n) {
                __half2 h = __floats2half2_rn(v10, v11);
                *(__half2*)&o[(long)(r0 + 8) * ld + cc] = h;
            }
        } else {
            float* o = (float*)op;
            if (r0 < n)     *(float2*)&o[(long)r0 * ld + cc] = make_float2(v00, v01);
            if (r0 + 8 < n) *(float2*)&o[(long)(r0 + 8) * ld + cc] = make_float2(v10, v11);
        }
    }
}

// ---------------- fused pool(xc) + whp + post + readout + log_softmax ----------------
// pool(xc@W+b) == pool(xc)@W + cnt*b  (exact linearity). 128 threads per graph.
__global__ void poolhead_k(const void* __restrict__ batch,
                           const float* __restrict__ whpW, const float* __restrict__ whpb,
                           const float* __restrict__ postW, const float* __restrict__ postb,
                           const float* __restrict__ roW, const float* __restrict__ rob,
                           float* __restrict__ out) {
    int g = blockIdx.x;
    int t = threadIdx.x;   // 128 threads
    int lo = 0, hi = NN;
    while (lo < hi) { int mid = (lo + hi) >> 1; if (ld_idx(batch, mid) < g) lo = mid + 1; else hi = mid; }
    int beg = lo;
    hi = NN;
    while (lo < hi) { int mid = (lo + hi) >> 1; if (ld_idx(batch, mid) < g + 1) lo = mid + 1; else hi = mid; }
    int end = lo;
    int cnt = end - beg;

    float acc = 0.f;
    for (int nd = beg; nd < end; nd++) acc += __half2float(g_xc[(long)nd * 128 + t]);

    __shared__ float sg[128], shH[64], sh1[64], sl[10];
    sg[t] = acc;
    __syncthreads();
    if (t < 64) {
        float a = cnt * whpb[t];
#pragma unroll 8
        for (int k = 0; k < 128; k++) a = fmaf(sg[k], whpW[k * 64 + t], a);
        shH[t] = a;
    }
    __syncthreads();
    if (t < 64) {
        float a = postb[t];
#pragma unroll
        for (int k = 0; k < 64; k++) a = fmaf(shH[k], postW[k * 64 + t], a);
        sh1[t] = fmaxf(a, 0.f);
    }
    __syncthreads();
    if (t < 10) {
        float r = rob[t];
#pragma unroll
        for (int k = 0; k < 64; k++) r = fmaf(sh1[k], roW[k * 10 + t], r);
        sl[t] = r;
    }
    __syncthreads();
    if (t == 0) {
        float m = sl[0];
#pragma unroll
        for (int c = 1; c < 10; c++) m = fmaxf(m, sl[c]);
        float sum = 0.f;
#pragma unroll
        for (int c = 0; c < 10; c++) sum += expf(sl[c] - m);
        float lse = m + logf(sum);
#pragma unroll
        for (int c = 0; c < 10; c++) out[g * 10 + c] = sl[c] - lse;
    }
}

// ---------------- launch ----------------
extern "C" void kernel_launch(void* const* d_in, const int* in_sizes, int n_in,
                              void* d_out, int out_size) {
    const float* x_in  = (const float*)d_in[0];
    const float* s_in  = (const float*)d_in[1];
    const void*  ei    = d_in[2];
    const void*  batch = d_in[3];
    const float* preW  = (const float*)d_in[4];
    const float* preb  = (const float*)d_in[5];
    const float* embW  = (const float*)d_in[6];
    const float* embb  = (const float*)d_in[7];
    const float* ginW1 = (const float*)d_in[8];
    const float* ginb1 = (const float*)d_in[9];
    const float* ginW2 = (const float*)d_in[10];
    const float* ginb2 = (const float*)d_in[11];
    const float* gcnW  = (const float*)d_in[12];
    const float* gcnb  = (const float*)d_in[13];
    const float* whpW  = (const float*)d_in[14];
    const float* whpb  = (const float*)d_in[15];
    const float* postW = (const float*)d_in[16];
    const float* postb = (const float*)d_in[17];
    const float* roW   = (const float*)d_in[18];
    const float* rob   = (const float*)d_in[19];
    float* out = (float*)d_out;

    void *p_xc, *p_y16, *p_hs16, *p_z16, *p_w16;
    cudaGetSymbolAddress(&p_xc, g_xc);
    cudaGetSymbolAddress(&p_y16, g_y16);
    cudaGetSymbolAddress(&p_hs16, g_hs16);
    cudaGetSymbolAddress(&p_z16, g_z16);
    cudaGetSymbolAddress(&p_w16, g_w16);
    __half* xc16 = (__half*)p_xc;
    __half* w16 = (__half*)p_w16;

    // dynamic smem: (128 + NOUT) * (K + 8) * 2 bytes
    const int SMPREMB = 256 * 152 * 2;  // 77824 (K=144, NOUT=128)
    const int SMDUAL  = 256 * 136 * 2;  // 69632 (K=128, NOUT=128)
    const int SM64    = 192 * 72 * 2;   // 27648 (K=64, NOUT=64)
    cudaFuncSetAttribute(hgemm_k<144, 128, 0, 1, 2>, cudaFuncAttributeMaxDynamicSharedMemorySize, SMPREMB);
    cudaFuncSetAttribute(hgemm_k<128, 128, 0, 1, 0>, cudaFuncAttributeMaxDynamicSharedMemorySize, SMDUAL);
    cudaFuncSetAttribute(hgemm_k<64, 64, 1, 1, 0>,   cudaFuncAttributeMaxDynamicSharedMemorySize, SM64);

    const int TB = 256;
    const int gridE = (EE + TB - 1) / TB;
    const int gridW = (NN * 32 + TB - 1) / TB;
    const int gridM = (NN + 127) / 128;   // 391 CTAs

    init_k<<<(2 * NN + TB - 1) / TB, TB>>>((const int*)ei);
    convw_k<<<(W_TOTAL + 255) / 256, 256>>>(ginW1, gcnW, ginW2, preW, embW);

    // CSR build
    hist_k<<<gridE, TB>>>(ei);
    scan_k<<<NB1, 1024>>>();
    fill_k<<<gridE, TB>>>(ei);

    // fused pre+emb: [x|s] (fp32) -> xc (fp16) in one GEMM
    hgemm_k<144, 128, 0, 1, 2><<<gridM, 256, SMPREMB>>>(
        x_in, 128, s_in, 16, w16 + W_PREMB, preb, embb, NN, xc16, 128, xc16 + 64, 128);

    for (int i = 0; i < LL; i++) {
        hgemm_k<128, 128, 0, 1, 0><<<gridM, 256, SMDUAL>>>(
            xc16, 128, nullptr, 0, w16 + W_DUAL + i * 16384, nullptr, nullptr, NN,
            p_y16, 64, p_hs16, 64);
        agg_fused_k<<<gridW, TB>>>(ginb1 + i * 64, gcnb + i * 64);
        hgemm_k<64, 64, 1, 1, 0><<<gridM, 256, SM64>>>(
            p_z16, 64, nullptr, 0, w16 + W_GIN2 + i * 4096, ginb2 + i * 64, nullptr, NN,
            xc16, 128, nullptr, 0);
    }

    poolhead_k<<<GG, 128>>>(batch, whpW, whpb, postW, postb, roW, rob, out);
}

// round 16
// speedup vs baseline: 1.1030x; 1.1030x over previous
#include <cuda_runtime.h>
#include <cuda_fp16.h>
#include <cstdint>

#define NN 50000
#define EE 800000
#define GG 500
#define LL 3
#define NB1 ((NN + 1023) / 1024)

// ---------------- mma.sync helpers (baseline PTX, no sm_103a features) ----------------
__device__ __forceinline__ uint32_t smem_u32(const void* p) {
    uint32_t a;
    asm("{ .reg .u64 t; cvta.to.shared.u64 t, %1; cvt.u32.u64 %0, t; }" : "=r"(a) : "l"(p));
    return a;
}
__device__ __forceinline__ void ldsm4(uint32_t& r0, uint32_t& r1, uint32_t& r2, uint32_t& r3,
                                      uint32_t addr) {
    asm volatile("ldmatrix.sync.aligned.m8n8.x4.shared.b16 {%0,%1,%2,%3}, [%4];"
                 : "=r"(r0), "=r"(r1), "=r"(r2), "=r"(r3) : "r"(addr));
}
__device__ __forceinline__ void mma16816(float* c, uint32_t a0, uint32_t a1, uint32_t a2,
                                         uint32_t a3, uint32_t b0, uint32_t b1) {
    asm volatile("mma.sync.aligned.m16n8k16.row.col.f32.f16.f16.f32 "
                 "{%0,%1,%2,%3}, {%4,%5,%6,%7}, {%8,%9}, {%0,%1,%2,%3};"
                 : "+f"(c[0]), "+f"(c[1]), "+f"(c[2]), "+f"(c[3])
                 : "r"(a0), "r"(a1), "r"(a2), "r"(a3), "r"(b0), "r"(b1));
}

// ---------------- scratch (static device globals; no allocation) ----------------
__device__ int    g_is64;
__device__ int    g_degi[NN];
__device__ float  g_degf[NN];
__device__ float  g_dinv[NN];
__device__ int    g_ptr[NN + 1];
__device__ int    g_cnt[NN];
__device__ int    g_bsum[64];
__device__ int    g_boff[65];
__device__ int    g_csrc[EE];
__device__ float  g_cw[EE];
__device__ __half g_xc[NN * 128];    // [x | s] concat fp16, row stride 128
__device__ __half g_y16[NN * 64];    // xc @ W1 fp16
__device__ __half g_hs16[NN * 64];   // s @ gcnW fp16
__device__ __half g_z16[NN * 64];    // relu(agg(y)+b1) fp16
__device__ float  g_x2[NN * 64];
__device__ __half g_w16[88064];      // weights fp16, [n][k] layouts

// weight buffer offsets (halves)
#define W_DUAL  0       // 3 x [128n][128k]  (n<64: ginW1; n>=64: gcn on k>=64, 0 else)
#define W_GIN2  49152   // 3 x [64][64]
#define W_WHP   61440   // [64][128]
#define W_PREMB 69632   // [128n][144k] (n<64: pre on k<128; n>=64: emb on k>=128; 0 else)
#define W_TOTAL 88064

// ---------------- index loading: int64 vs int32 auto-detect ----------------
__device__ __forceinline__ int ld_idx(const void* p, long i) {
    if (g_is64) return (int)((const long long*)p)[i];
    return ((const int*)p)[i];
}

// ---------------- init: zero counters + dtype detect ----------------
__global__ void init_k(const int* w) {
    int i = blockIdx.x * blockDim.x + threadIdx.x;
    if (i < NN) g_degi[i] = 0;
    else if (i < 2 * NN) g_cnt[i - NN] = 0;
    if (i == 0) {
        int nz = 0;
#pragma unroll
        for (int j = 0; j < 8; j++)
            if (w[2 * j + 1] != 0) nz++;
        g_is64 = (nz == 0) ? 1 : 0;
    }
}

// ---------------- weight convert + transpose to fp16 ----------------
__global__ void convw_k(const float* __restrict__ gin1, const float* __restrict__ gcn,
                        const float* __restrict__ gin2, const float* __restrict__ whp,
                        const float* __restrict__ pre, const float* __restrict__ emb) {
    int idx = blockIdx.x * blockDim.x + threadIdx.x;
    if (idx >= W_TOTAL) return;
    float v;
    if (idx < 49152) {            // dual: [l][n=128][k=128]
        int l = idx / 16384, r = idx % 16384, n = r / 128, k = r % 128;
        if (n < 64) v = gin1[l * 8192 + k * 64 + n];
        else if (k >= 64) v = gcn[l * 4096 + (k - 64) * 64 + (n - 64)];
        else v = 0.f;
    } else if (idx < 61440) {     // ginW2 [l][64][64]
        int r0 = idx - 49152; int l = r0 / 4096, r = r0 % 4096, n = r / 64, k = r % 64;
        v = gin2[l * 4096 + k * 64 + n];
    } else if (idx < 69632) {     // whp [128][64] -> [n][k]
        int r = idx - W_WHP; int n = r / 128, k = r % 128;
        v = whp[k * 64 + n];
    } else {                      // premb: [n=128][k=144]
        int r = idx - W_PREMB; int n = r / 144, k = r % 144;
        if (n < 64) v = (k < 128) ? pre[k * 64 + n] : 0.f;
        else v = (k >= 128) ? emb[(k - 128) * 64 + (n - 64)] : 0.f;
    }
    g_w16[idx] = __float2half_rn(v);
}

// ---------------- degree histogram ----------------
__global__ void hist_k(const void* ei) {
    int e = blockIdx.x * blockDim.x + threadIdx.x;
    if (e < EE) {
        int d = ld_idx(ei, (long)EE + e);
        atomicAdd(&g_degi[d], 1);
    }
}

// ---------------- 3-phase scan (proven R14) ----------------
__global__ void scan1_k() {
    __shared__ int sh[1024];
    int tid = threadIdx.x;
    int i = blockIdx.x * 1024 + tid;
    int v = (i < NN) ? g_degi[i] : 0;
    if (i < NN) {
        float d = (float)(v + 1);
        g_degf[i] = d;
        g_dinv[i] = rsqrtf(d);
    }
    sh[tid] = v;
    __syncthreads();
    for (int off = 1; off < 1024; off <<= 1) {
        int t = (tid >= off) ? sh[tid - off] : 0;
        __syncthreads();
        sh[tid] += t;
        __syncthreads();
    }
    int incl = sh[tid];
    if (i < NN) g_ptr[i] = incl - v;
    if (tid == 1023) g_bsum[blockIdx.x] = incl;
}

__global__ void scan2_k() {
    __shared__ int sh[64];
    int t = threadIdx.x;
    int v = (t < NB1) ? g_bsum[t] : 0;
    sh[t] = v;
    __syncthreads();
    for (int off = 1; off < 64; off <<= 1) {
        int x = (t >= off) ? sh[t - off] : 0;
        __syncthreads();
        sh[t] += x;
        __syncthreads();
    }
    if (t <= NB1) g_boff[t] = sh[t] - v;
}

__global__ void scan3_k() {
    int i = blockIdx.x * blockDim.x + threadIdx.x;
    if (i < NN) g_ptr[i] += g_boff[i >> 10];
    if (i == 0) g_ptr[NN] = g_boff[NB1];
}

// ---------------- CSR fill ----------------
__global__ void fill_k(const void* ei) {
    int e = blockIdx.x * blockDim.x + threadIdx.x;
    if (e < EE) {
        int sn = ld_idx(ei, e);
        int dn = ld_idx(ei, (long)EE + e);
        int pos = g_ptr[dn] + atomicAdd(&g_cnt[dn], 1);
        g_csrc[pos] = sn;
        g_cw[pos] = g_dinv[sn] * g_dinv[dn];
    }
}

// ---------------- fused GIN(y) + GCN(hs) aggregation, fp16 gathers, 4-edge ILP ----------------
__global__ void agg_fused_k(const float* __restrict__ b1, const float* __restrict__ bg) {
    int nd = (blockIdx.x * blockDim.x + threadIdx.x) >> 5;
    if (nd >= NN) return;
    int lane = threadIdx.x & 31;
    int l4 = lane & 15;
    bool isY = lane < 16;
    const uint2* base = isY ? (const uint2*)g_y16 : (const uint2*)g_hs16;
    int b = g_ptr[nd], e = g_ptr[nd + 1];
    float4 a0 = make_float4(0.f, 0.f, 0.f, 0.f);
    float4 a1 = make_float4(0.f, 0.f, 0.f, 0.f);
    float4 a2 = make_float4(0.f, 0.f, 0.f, 0.f);
    float4 a3 = make_float4(0.f, 0.f, 0.f, 0.f);
    int i = b;
    for (; i + 3 < e; i += 4) {
        int s0 = g_csrc[i], s1 = g_csrc[i + 1], s2 = g_csrc[i + 2], s3 = g_csrc[i + 3];
        float w0 = isY ? 1.f : g_cw[i];
        float w1 = isY ? 1.f : g_cw[i + 1];
        float w2 = isY ? 1.f : g_cw[i + 2];
        float w3 = isY ? 1.f : g_cw[i + 3];
        uint2 u0 = base[(long)s0 * 16 + l4];
        uint2 u1 = base[(long)s1 * 16 + l4];
        uint2 u2 = base[(long)s2 * 16 + l4];
        uint2 u3 = base[(long)s3 * 16 + l4];
        float2 p0 = __half22float2(*(const __half2*)&u0.x);
        float2 p1 = __half22float2(*(const __half2*)&u0.y);
        a0.x = fmaf(w0, p0.x, a0.x); a0.y = fmaf(w0, p0.y, a0.y);
        a0.z = fmaf(w0, p1.x, a0.z); a0.w = fmaf(w0, p1.y, a0.w);
        float2 q0 = __half22float2(*(const __half2*)&u1.x);
        float2 q1 = __half22float2(*(const __half2*)&u1.y);
        a1.x = fmaf(w1, q0.x, a1.x); a1.y = fmaf(w1, q0.y, a1.y);
        a1.z = fmaf(w1, q1.x, a1.z); a1.w = fmaf(w1, q1.y, a1.w);
        float2 r0 = __half22float2(*(const __half2*)&u2.x);
        float2 r1 = __half22float2(*(const __half2*)&u2.y);
        a2.x = fmaf(w2, r0.x, a2.x); a2.y = fmaf(w2, r0.y, a2.y);
        a2.z = fmaf(w2, r1.x, a2.z); a2.w = fmaf(w2, r1.y, a2.w);
        float2 t0 = __half22float2(*(const __half2*)&u3.x);
        float2 t1 = __half22float2(*(const __half2*)&u3.y);
        a3.x = fmaf(w3, t0.x, a3.x); a3.y = fmaf(w3, t0.y, a3.y);
        a3.z = fmaf(w3, t1.x, a3.z); a3.w = fmaf(w3, t1.y, a3.w);
    }
    for (; i < e; i++) {
        int s0 = g_csrc[i];
        float w0 = isY ? 1.f : g_cw[i];
        uint2 u0 = base[(long)s0 * 16 + l4];
        float2 p0 = __half22float2(*(const __half2*)&u0.x);
        float2 p1 = __half22float2(*(const __half2*)&u0.y);
        a0.x = fmaf(w0, p0.x, a0.x); a0.y = fmaf(w0, p0.y, a0.y);
        a0.z = fmaf(w0, p1.x, a0.z); a0.w = fmaf(w0, p1.y, a0.w);
    }
    a0.x += a1.x + a2.x + a3.x;
    a0.y += a1.y + a2.y + a3.y;
    a0.z += a1.z + a2.z + a3.z;
    a0.w += a1.w + a2.w + a3.w;
    float ws = isY ? 1.f : (1.f / g_degf[nd]);
    {
        uint2 us = base[(long)nd * 16 + l4];
        float2 p0 = __half22float2(*(const __half2*)&us.x);
        float2 p1 = __half22float2(*(const __half2*)&us.y);
        a0.x = fmaf(ws, p0.x, a0.x); a0.y = fmaf(ws, p0.y, a0.y);
        a0.z = fmaf(ws, p1.x, a0.z); a0.w = fmaf(ws, p1.y, a0.w);
    }
    if (isY) {
        float r0 = fmaxf(a0.x + b1[4 * l4 + 0], 0.f);
        float r1 = fmaxf(a0.y + b1[4 * l4 + 1], 0.f);
        float r2 = fmaxf(a0.z + b1[4 * l4 + 2], 0.f);
        float r3 = fmaxf(a0.w + b1[4 * l4 + 3], 0.f);
        __half2 h01 = __floats2half2_rn(r0, r1);
        __half2 h23 = __floats2half2_rn(r2, r3);
        uint2 pk; pk.x = *(const unsigned*)&h01; pk.y = *(const unsigned*)&h23;
        ((uint2*)g_z16)[(long)nd * 16 + l4] = pk;
    } else {
        float r0 = tanhf(a0.x + bg[4 * l4 + 0]);
        float r1 = tanhf(a0.y + bg[4 * l4 + 1]);
        float r2 = tanhf(a0.z + bg[4 * l4 + 2]);
        float r3 = tanhf(a0.w + bg[4 * l4 + 3]);
        __half2 h01 = __floats2half2_rn(r0, r1);
        __half2 h23 = __floats2half2_rn(r2, r3);
        uint2 pk; pk.x = *(const unsigned*)&h01; pk.y = *(const unsigned*)&h23;
        ((uint2*)g_xc)[(long)nd * 32 + 16 + l4] = pk;
    }
}

// ---------------- HMMA GEMM ----------------
// F32IN: 0 = fp16 single input; 2 = fp32 concat (cols<128 from in/ldin, rest from in2/ldin2).
// NOUT=128 splits outputs: cols<64 -> outA (+biasA), cols>=64 -> outB (+biasB).
template <int K, int NOUT, int ACT, int HOUT, int F32IN>
__global__ void __launch_bounds__(256) hgemm_k(
        const void* __restrict__ in, int ldin,
        const void* __restrict__ in2, int ldin2,
        const __half* __restrict__ wt,
        const float* __restrict__ biasA, const float* __restrict__ biasB, int n,
        void* __restrict__ outA, int ldA, void* __restrict__ outB, int ldB) {
    constexpr int KP = K + 8;
    constexpr int KQ = K / 4;
    extern __shared__ __half dsm[];
    __half* sA = dsm;                     // [128][KP]
    __half* sB = dsm + 128 * KP;          // [NOUT][KP]

    int tid = threadIdx.x;
    int w = tid >> 5, lane = tid & 31;
    int rowBase = blockIdx.x * 128;

    for (int idx = tid; idx < 128 * KQ; idx += 256) {
        int r = idx / KQ, q = idx - r * KQ;
        int gr = rowBase + r;
        uint2 pk = make_uint2(0u, 0u);
        if (gr < n) {
            if (F32IN == 2) {
                int col = 4 * q;
                const float* src = (col < 128) ? &((const float*)in)[(long)gr * ldin + col]
                                               : &((const float*)in2)[(long)gr * ldin2 + (col - 128)];
                float4 v = *(const float4*)src;
                __half2 h0 = __floats2half2_rn(v.x, v.y);
                __half2 h1 = __floats2half2_rn(v.z, v.w);
                pk.x = *(const unsigned*)&h0;
                pk.y = *(const unsigned*)&h1;
            } else {
                pk = *(const uint2*)&((const __half*)in)[(long)gr * ldin + 4 * q];
            }
        }
        *(uint2*)&sA[r * KP + 4 * q] = pk;
    }
    for (int idx = tid; idx < NOUT * KQ; idx += 256) {
        int r = idx / KQ, q = idx - r * KQ;
        *(uint2*)&sB[r * KP + 4 * q] = *(const uint2*)&wt[(long)r * K + 4 * q];
    }
    __syncthreads();

    constexpr int NT = NOUT / 8;
    float acc[NT][4];
#pragma unroll
    for (int t = 0; t < NT; t++)
#pragma unroll
        for (int j = 0; j < 4; j++) acc[t][j] = 0.f;

    uint32_t aAddr = smem_u32(&sA[(16 * w + (lane & 15)) * KP + ((lane >> 4) << 3)]);
    int bRow = (lane & 7) + ((lane >> 4) << 3);
    int bCol = ((lane >> 3) & 1) << 3;
    uint32_t bAddr0 = smem_u32(&sB[bRow * KP + bCol]);

#pragma unroll
    for (int kk = 0; kk < K / 16; kk++) {
        uint32_t a0, a1, a2, a3;
        ldsm4(a0, a1, a2, a3, aAddr + kk * 32);
#pragma unroll
        for (int ntp = 0; ntp < NT / 2; ntp++) {
            uint32_t b0, b1, b2, b3;
            ldsm4(b0, b1, b2, b3, bAddr0 + (ntp * 16 * KP + kk * 16) * 2);
            mma16816(acc[2 * ntp],     a0, a1, a2, a3, b0, b1);
            mma16816(acc[2 * ntp + 1], a0, a1, a2, a3, b2, b3);
        }
    }

    int r0 = rowBase + 16 * w + (lane >> 2);
    int cb = (lane & 3) * 2;
#pragma unroll
    for (int nt = 0; nt < NT; nt++) {
        int c = nt * 8 + cb;
        float v00 = acc[nt][0], v01 = acc[nt][1], v10 = acc[nt][2], v11 = acc[nt][3];
        const float* bp = (NOUT == 128 && c >= 64) ? biasB : biasA;
        int cc = (NOUT == 128 && c >= 64) ? c - 64 : c;
        if (bp) {
            float bc0 = bp[cc], bc1 = bp[cc + 1];
            v00 += bc0; v01 += bc1; v10 += bc0; v11 += bc1;
        }
        if (ACT) {
            v00 = fmaxf(v00, 0.f); v01 = fmaxf(v01, 0.f);
            v10 = fmaxf(v10, 0.f); v11 = fmaxf(v11, 0.f);
        }
        void* op = outA;
        int ld = ldA;
        if (NOUT == 128 && c >= 64) { op = outB; ld = ldB; }
        if (HOUT) {
            __half* o = (__half*)op;
            if (r0 < n) {
                __half2 h = __floats2half2_rn(v00, v01);
                *(__half2*)&o[(long)r0 * ld + cc] = h;
            }
            if (r0 + 8 < n) {
                __half2 h = __floats2half2_rn(v10, v11);
                *(__half2*)&o[(long)(r0 + 8) * ld + cc] = h;
            }
        } else {
            float* o = (float*)op;
            if (r0 < n)     *(float2*)&o[(long)r0 * ld + cc] = make_float2(v00, v01);
            if (r0 + 8 < n) *(float2*)&o[(long)(r0 + 8) * ld + cc] = make_float2(v10, v11);
        }
    }
}

// ---------------- fused global add pool + post + readout + log_softmax (R14 proven) ----------------
__global__ void poolhead_k(const void* __restrict__ batch,
                           const float* __restrict__ postW, const float* __restrict__ postb,
                           const float* __restrict__ roW, const float* __restrict__ rob,
                           float* __restrict__ out) {
    int g = blockIdx.x;
    int t = threadIdx.x;
    int lo = 0, hi = NN;
    while (lo < hi) { int mid = (lo + hi) >> 1; if (ld_idx(batch, mid) < g) lo = mid + 1; else hi = mid; }
    int beg = lo;
    hi = NN;
    while (lo < hi) { int mid = (lo + hi) >> 1; if (ld_idx(batch, mid) < g + 1) lo = mid + 1; else hi = mid; }
    int end = lo;

    float acc = 0.f;
    for (int nd = beg; nd < end; nd++) acc += g_x2[(long)nd * 64 + t];

    __shared__ float sg[64], sh1[64], sl[10];
    sg[t] = acc;
    __syncthreads();
    float a = postb[t];
#pragma unroll
    for (int k = 0; k < 64; k++) a = fmaf(sg[k], postW[k * 64 + t], a);
    sh1[t] = fmaxf(a, 0.f);
    __syncthreads();
    if (t < 10) {
        float r = rob[t];
#pragma unroll
        for (int k = 0; k < 64; k++) r = fmaf(sh1[k], roW[k * 10 + t], r);
        sl[t] = r;
    }
    __syncthreads();
    if (t == 0) {
        float m = sl[0];
#pragma unroll
        for (int c = 1; c < 10; c++) m = fmaxf(m, sl[c]);
        float sum = 0.f;
#pragma unroll
        for (int c = 0; c < 10; c++) sum += expf(sl[c] - m);
        float lse = m + logf(sum);
#pragma unroll
        for (int c = 0; c < 10; c++) out[g * 10 + c] = sl[c] - lse;
    }
}

// ---------------- launch ----------------
extern "C" void kernel_launch(void* const* d_in, const int* in_sizes, int n_in,
                              void* d_out, int out_size) {
    const float* x_in  = (const float*)d_in[0];
    const float* s_in  = (const float*)d_in[1];
    const void*  ei    = d_in[2];
    const void*  batch = d_in[3];
    const float* preW  = (const float*)d_in[4];
    const float* preb  = (const float*)d_in[5];
    const float* embW  = (const float*)d_in[6];
    const float* embb  = (const float*)d_in[7];
    const float* ginW1 = (const float*)d_in[8];
    const float* ginb1 = (const float*)d_in[9];
    const float* ginW2 = (const float*)d_in[10];
    const float* ginb2 = (const float*)d_in[11];
    const float* gcnW  = (const float*)d_in[12];
    const float* gcnb  = (const float*)d_in[13];
    const float* whpW  = (const float*)d_in[14];
    const float* whpb  = (const float*)d_in[15];
    const float* postW = (const float*)d_in[16];
    const float* postb = (const float*)d_in[17];
    const float* roW   = (const float*)d_in[18];
    const float* rob   = (const float*)d_in[19];
    float* out = (float*)d_out;

    void *p_xc, *p_y16, *p_hs16, *p_z16, *p_x2, *p_w16;
    cudaGetSymbolAddress(&p_xc, g_xc);
    cudaGetSymbolAddress(&p_y16, g_y16);
    cudaGetSymbolAddress(&p_hs16, g_hs16);
    cudaGetSymbolAddress(&p_z16, g_z16);
    cudaGetSymbolAddress(&p_x2, g_x2);
    cudaGetSymbolAddress(&p_w16, g_w16);
    __half* xc16 = (__half*)p_xc;
    __half* w16 = (__half*)p_w16;

    // dynamic smem: (128 + NOUT) * (K + 8) * 2 bytes
    const int SMPREMB = 256 * 152 * 2;  // 77824 (K=144, NOUT=128)
    const int SMDUAL  = 256 * 136 * 2;  // 69632 (K=128, NOUT=128)
    const int SM128   = 192 * 136 * 2;  // 52224 (K=128, NOUT=64)
    const int SM64    = 192 * 72 * 2;   // 27648 (K=64, NOUT=64)
    cudaFuncSetAttribute(hgemm_k<144, 128, 0, 1, 2>, cudaFuncAttributeMaxDynamicSharedMemorySize, SMPREMB);
    cudaFuncSetAttribute(hgemm_k<128, 128, 0, 1, 0>, cudaFuncAttributeMaxDynamicSharedMemorySize, SMDUAL);
    cudaFuncSetAttribute(hgemm_k<64, 64, 1, 1, 0>,   cudaFuncAttributeMaxDynamicSharedMemorySize, SM64);
    cudaFuncSetAttribute(hgemm_k<128, 64, 0, 0, 0>,  cudaFuncAttributeMaxDynamicSharedMemorySize, SM128);

    const int TB = 256;
    const int gridE = (EE + TB - 1) / TB;
    const int gridN = (NN + TB - 1) / TB;
    const int gridW = (NN * 32 + TB - 1) / TB;
    const int gridM = (NN + 127) / 128;   // 391 CTAs

    init_k<<<(2 * NN + TB - 1) / TB, TB>>>((const int*)ei);
    convw_k<<<(W_TOTAL + 255) / 256, 256>>>(ginW1, gcnW, ginW2, whpW, preW, embW);

    // CSR build (proven 3-phase scan)
    hist_k<<<gridE, TB>>>(ei);
    scan1_k<<<NB1, 1024>>>();
    scan2_k<<<1, 64>>>();
    scan3_k<<<gridN, TB>>>();
    fill_k<<<gridE, TB>>>(ei);

    // fused pre+emb: [x|s] (fp32) -> xc (fp16) in one GEMM
    hgemm_k<144, 128, 0, 1, 2><<<gridM, 256, SMPREMB>>>(
        x_in, 128, s_in, 16, w16 + W_PREMB, preb, embb, NN, xc16, 128, xc16 + 64, 128);

    for (int i = 0; i < LL; i++) {
        hgemm_k<128, 128, 0, 1, 0><<<gridM, 256, SMDUAL>>>(
            xc16, 128, nullptr, 0, w16 + W_DUAL + i * 16384, nullptr, nullptr, NN,
            p_y16, 64, p_hs16, 64);
        agg_fused_k<<<gridW, TB>>>(ginb1 + i * 64, gcnb + i * 64);
        hgemm_k<64, 64, 1, 1, 0><<<gridM, 256, SM64>>>(
            p_z16, 64, nullptr, 0, w16 + W_GIN2 + i * 4096, ginb2 + i * 64, nullptr, NN,
            xc16, 128, nullptr, 0);
    }

    hgemm_k<128, 64, 0, 0, 0><<<gridM, 256, SM128>>>(
        xc16, 128, nullptr, 0, w16 + W_WHP, whpb, nullptr, NN, p_x2, 64, nullptr, 0);
    poolhead_k<<<GG, 64>>>(batch, postW, postb, roW, rob, out);
}

// round 17
// speedup vs baseline: 1.2875x; 1.1672x over previous
#include <cuda_runtime.h>
#include <cuda_fp16.h>
#include <cstdint>

#define NN 50000
#define EE 800000
#define GG 500
#define LL 3
#define NB1 ((NN + 1023) / 1024)

// ---------------- mma.sync helpers (baseline PTX, no sm_103a features) ----------------
__device__ __forceinline__ uint32_t smem_u32(const void* p) {
    uint32_t a;
    asm("{ .reg .u64 t; cvta.to.shared.u64 t, %1; cvt.u32.u64 %0, t; }" : "=r"(a) : "l"(p));
    return a;
}
__device__ __forceinline__ void ldsm4(uint32_t& r0, uint32_t& r1, uint32_t& r2, uint32_t& r3,
                                      uint32_t addr) {
    asm volatile("ldmatrix.sync.aligned.m8n8.x4.shared.b16 {%0,%1,%2,%3}, [%4];"
                 : "=r"(r0), "=r"(r1), "=r"(r2), "=r"(r3) : "r"(addr));
}
__device__ __forceinline__ void mma16816(float* c, uint32_t a0, uint32_t a1, uint32_t a2,
                                         uint32_t a3, uint32_t b0, uint32_t b1) {
    asm volatile("mma.sync.aligned.m16n8k16.row.col.f32.f16.f16.f32 "
                 "{%0,%1,%2,%3}, {%4,%5,%6,%7}, {%8,%9}, {%0,%1,%2,%3};"
                 : "+f"(c[0]), "+f"(c[1]), "+f"(c[2]), "+f"(c[3])
                 : "r"(a0), "r"(a1), "r"(a2), "r"(a3), "r"(b0), "r"(b1));
}

// ---------------- scratch (static device globals; no allocation) ----------------
__device__ int    g_is64;
__device__ int    g_degi[NN];
__device__ float  g_degf[NN];
__device__ float  g_dinv[NN];
__device__ int    g_ptr[NN + 1];
__device__ int    g_cnt[NN];
__device__ int    g_bsum[64];
__device__ int    g_boff[65];
__device__ int    g_csrc[EE];
__device__ float  g_cw[EE];
__device__ __half g_xc[NN * 128];    // [x | s] concat fp16, row stride 128
__device__ __half g_y16[NN * 64];    // xc @ W1 fp16
__device__ __half g_hs16[NN * 64];   // s @ gcnW fp16
__device__ __half g_z16[NN * 64];    // relu(agg(y)+b1) fp16
__device__ float  g_x2[NN * 64];
__device__ __half g_w16[78848];      // all weights fp16, [n][k] layouts

// weight buffer offsets (halves)
#define W_DUAL 0        // 3 x [128n][128k]  (n<64: ginW1; n>=64: gcn on k>=64, 0 else)
#define W_GIN2 49152    // 3 x [64][64]
#define W_WHP  61440    // [64][128]
#define W_PRE  69632    // [64][128]
#define W_EMB  77824    // [64][16]
#define W_TOTAL 78848

// ---------------- index loading: int64 vs int32 auto-detect ----------------
__device__ __forceinline__ int ld_idx(const void* p, long i) {
    if (g_is64) return (int)((const long long*)p)[i];
    return ((const int*)p)[i];
}

__global__ void detect_k(const int* w) {
    if (blockIdx.x == 0 && threadIdx.x == 0) {
        int nz = 0;
#pragma unroll
        for (int j = 0; j < 8; j++)
            if (w[2 * j + 1] != 0) nz++;
        g_is64 = (nz == 0) ? 1 : 0;
    }
}

// ---------------- weight convert + transpose to fp16 ----------------
__global__ void convw_k(const float* __restrict__ gin1, const float* __restrict__ gcn,
                        const float* __restrict__ gin2, const float* __restrict__ whp,
                        const float* __restrict__ pre, const float* __restrict__ emb) {
    int idx = blockIdx.x * blockDim.x + threadIdx.x;
    if (idx >= W_TOTAL) return;
    float v;
    if (idx < 49152) {            // dual: [l][n=128][k=128]
        int l = idx / 16384, r = idx % 16384, n = r / 128, k = r % 128;
        if (n < 64) v = gin1[l * 8192 + k * 64 + n];
        else if (k >= 64) v = gcn[l * 4096 + (k - 64) * 64 + (n - 64)];
        else v = 0.f;
    } else if (idx < 61440) {     // ginW2 [l][64][64]
        int r0 = idx - 49152; int l = r0 / 4096, r = r0 % 4096, n = r / 64, k = r % 64;
        v = gin2[l * 4096 + k * 64 + n];
    } else if (idx < 69632) {     // whp [128][64] -> [n][k]
        int r = idx - 61440; int n = r / 128, k = r % 128;
        v = whp[k * 64 + n];
    } else if (idx < 77824) {     // pre
        int r = idx - 69632; int n = r / 128, k = r % 128;
        v = pre[k * 64 + n];
    } else {                      // emb [16][64]
        int r = idx - 77824; int n = r / 16, k = r % 16;
        v = emb[k * 64 + n];
    }
    g_w16[idx] = __float2half_rn(v);
}

// ---------------- degree histogram ----------------
__global__ void hist_k(const void* ei) {
    int e = blockIdx.x * blockDim.x + threadIdx.x;
    if (e < EE) {
        int d = ld_idx(ei, (long)EE + e);
        atomicAdd(&g_degi[d], 1);
    }
}

// ---------------- 3-phase scan (proven) ----------------
__global__ void scan1_k() {
    __shared__ int sh[1024];
    int tid = threadIdx.x;
    int i = blockIdx.x * 1024 + tid;
    int v = (i < NN) ? g_degi[i] : 0;
    if (i < NN) {
        float d = (float)(v + 1);
        g_degf[i] = d;
        g_dinv[i] = rsqrtf(d);
    }
    sh[tid] = v;
    __syncthreads();
    for (int off = 1; off < 1024; off <<= 1) {
        int t = (tid >= off) ? sh[tid - off] : 0;
        __syncthreads();
        sh[tid] += t;
        __syncthreads();
    }
    int incl = sh[tid];
    if (i < NN) g_ptr[i] = incl - v;
    if (tid == 1023) g_bsum[blockIdx.x] = incl;
}

__global__ void scan2_k() {
    __shared__ int sh[64];
    int t = threadIdx.x;
    int v = (t < NB1) ? g_bsum[t] : 0;
    sh[t] = v;
    __syncthreads();
    for (int off = 1; off < 64; off <<= 1) {
        int x = (t >= off) ? sh[t - off] : 0;
        __syncthreads();
        sh[t] += x;
        __syncthreads();
    }
    if (t <= NB1) g_boff[t] = sh[t] - v;
}

__global__ void scan3_k() {
    int i = blockIdx.x * blockDim.x + threadIdx.x;
    if (i < NN) g_ptr[i] += g_boff[i >> 10];
    if (i == 0) g_ptr[NN] = g_boff[NB1];
}

// ---------------- CSR fill ----------------
__global__ void fill_k(const void* ei) {
    int e = blockIdx.x * blockDim.x + threadIdx.x;
    if (e < EE) {
        int sn = ld_idx(ei, e);
        int dn = ld_idx(ei, (long)EE + e);
        int pos = g_ptr[dn] + atomicAdd(&g_cnt[dn], 1);
        g_csrc[pos] = sn;
        g_cw[pos] = g_dinv[sn] * g_dinv[dn];
    }
}

// ---------------- fused GIN(y) + GCN(hs) aggregation, fp16 gathers (R14: 2-edge) ----------------
__global__ void agg_fused_k(const float* __restrict__ b1, const float* __restrict__ bg) {
    int nd = (blockIdx.x * blockDim.x + threadIdx.x) >> 5;
    if (nd >= NN) return;
    int lane = threadIdx.x & 31;
    int l4 = lane & 15;
    bool isY = lane < 16;
    const uint2* base = isY ? (const uint2*)g_y16 : (const uint2*)g_hs16;
    int b = g_ptr[nd], e = g_ptr[nd + 1];
    float4 a0 = make_float4(0.f, 0.f, 0.f, 0.f);
    float4 a1 = make_float4(0.f, 0.f, 0.f, 0.f);
    int i = b;
    for (; i + 1 < e; i += 2) {
        int s0 = g_csrc[i], s1 = g_csrc[i + 1];
        float w0 = isY ? 1.f : g_cw[i];
        float w1 = isY ? 1.f : g_cw[i + 1];
        uint2 u0 = base[(long)s0 * 16 + l4];
        uint2 u1 = base[(long)s1 * 16 + l4];
        float2 p0 = __half22float2(*(const __half2*)&u0.x);
        float2 p1 = __half22float2(*(const __half2*)&u0.y);
        float2 q0 = __half22float2(*(const __half2*)&u1.x);
        float2 q1 = __half22float2(*(const __half2*)&u1.y);
        a0.x = fmaf(w0, p0.x, a0.x); a0.y = fmaf(w0, p0.y, a0.y);
        a0.z = fmaf(w0, p1.x, a0.z); a0.w = fmaf(w0, p1.y, a0.w);
        a1.x = fmaf(w1, q0.x, a1.x); a1.y = fmaf(w1, q0.y, a1.y);
        a1.z = fmaf(w1, q1.x, a1.z); a1.w = fmaf(w1, q1.y, a1.w);
    }
    if (i < e) {
        int s0 = g_csrc[i];
        float w0 = isY ? 1.f : g_cw[i];
        uint2 u0 = base[(long)s0 * 16 + l4];
        float2 p0 = __half22float2(*(const __half2*)&u0.x);
        float2 p1 = __half22float2(*(const __half2*)&u0.y);
        a0.x = fmaf(w0, p0.x, a0.x); a0.y = fmaf(w0, p0.y, a0.y);
        a0.z = fmaf(w0, p1.x, a0.z); a0.w = fmaf(w0, p1.y, a0.w);
    }
    a0.x += a1.x; a0.y += a1.y; a0.z += a1.z; a0.w += a1.w;
    float ws = isY ? 1.f : (1.f / g_degf[nd]);
    {
        uint2 us = base[(long)nd * 16 + l4];
        float2 p0 = __half22float2(*(const __half2*)&us.x);
        float2 p1 = __half22float2(*(const __half2*)&us.y);
        a0.x = fmaf(ws, p0.x, a0.x); a0.y = fmaf(ws, p0.y, a0.y);
        a0.z = fmaf(ws, p1.x, a0.z); a0.w = fmaf(ws, p1.y, a0.w);
    }
    if (isY) {
        float r0 = fmaxf(a0.x + b1[4 * l4 + 0], 0.f);
        float r1 = fmaxf(a0.y + b1[4 * l4 + 1], 0.f);
        float r2 = fmaxf(a0.z + b1[4 * l4 + 2], 0.f);
        float r3 = fmaxf(a0.w + b1[4 * l4 + 3], 0.f);
        __half2 h01 = __floats2half2_rn(r0, r1);
        __half2 h23 = __floats2half2_rn(r2, r3);
        uint2 pk; pk.x = *(const unsigned*)&h01; pk.y = *(const unsigned*)&h23;
        ((uint2*)g_z16)[(long)nd * 16 + l4] = pk;
    } else {
        float r0 = tanhf(a0.x + bg[4 * l4 + 0]);
        float r1 = tanhf(a0.y + bg[4 * l4 + 1]);
        float r2 = tanhf(a0.z + bg[4 * l4 + 2]);
        float r3 = tanhf(a0.w + bg[4 * l4 + 3]);
        __half2 h01 = __floats2half2_rn(r0, r1);
        __half2 h23 = __floats2half2_rn(r2, r3);
        uint2 pk; pk.x = *(const unsigned*)&h01; pk.y = *(const unsigned*)&h23;
        ((uint2*)g_xc)[(long)nd * 32 + 16 + l4] = pk;
    }
}

// ---------------- HMMA GEMM (R14 proven) ----------------
// F32IN=1: fp32 input converted during smem fill. NOUT=128 splits outputs at col 64.
template <int K, int NOUT, int ACT, int HOUT, int F32IN>
__global__ void __launch_bounds__(256) hgemm_k(
        const void* __restrict__ in, int ldin,
        const __half* __restrict__ wt, const float* __restrict__ bias, int n,
        void* __restrict__ outA, int ldA, void* __restrict__ outB, int ldB) {
    constexpr int KP = K + 8;
    constexpr int KQ = K / 4;
    extern __shared__ __half dsm[];
    __half* sA = dsm;                     // [128][KP]
    __half* sB = dsm + 128 * KP;          // [NOUT][KP]

    int tid = threadIdx.x;
    int w = tid >> 5, lane = tid & 31;
    int rowBase = blockIdx.x * 128;

    for (int idx = tid; idx < 128 * KQ; idx += 256) {
        int r = idx / KQ, q = idx - r * KQ;
        int gr = rowBase + r;
        uint2 pk = make_uint2(0u, 0u);
        if (gr < n) {
            if (F32IN) {
                float4 v = *(const float4*)&((const float*)in)[(long)gr * ldin + 4 * q];
                __half2 h0 = __floats2half2_rn(v.x, v.y);
                __half2 h1 = __floats2half2_rn(v.z, v.w);
                pk.x = *(const unsigned*)&h0;
                pk.y = *(const unsigned*)&h1;
            } else {
                pk = *(const uint2*)&((const __half*)in)[(long)gr * ldin + 4 * q];
            }
        }
        *(uint2*)&sA[r * KP + 4 * q] = pk;
    }
    for (int idx = tid; idx < NOUT * KQ; idx += 256) {
        int r = idx / KQ, q = idx - r * KQ;
        *(uint2*)&sB[r * KP + 4 * q] = *(const uint2*)&wt[(long)r * K + 4 * q];
    }
    __syncthreads();

    constexpr int NT = NOUT / 8;
    float acc[NT][4];
#pragma unroll
    for (int t = 0; t < NT; t++)
#pragma unroll
        for (int j = 0; j < 4; j++) acc[t][j] = 0.f;

    uint32_t aAddr = smem_u32(&sA[(16 * w + (lane & 15)) * KP + ((lane >> 4) << 3)]);
    int bRow = (lane & 7) + ((lane >> 4) << 3);
    int bCol = ((lane >> 3) & 1) << 3;
    uint32_t bAddr0 = smem_u32(&sB[bRow * KP + bCol]);

#pragma unroll
    for (int kk = 0; kk < K / 16; kk++) {
        uint32_t a0, a1, a2, a3;
        ldsm4(a0, a1, a2, a3, aAddr + kk * 32);
#pragma unroll
        for (int ntp = 0; ntp < NT / 2; ntp++) {
            uint32_t b0, b1, b2, b3;
            ldsm4(b0, b1, b2, b3, bAddr0 + (ntp * 16 * KP + kk * 16) * 2);
            mma16816(acc[2 * ntp],     a0, a1, a2, a3, b0, b1);
            mma16816(acc[2 * ntp + 1], a0, a1, a2, a3, b2, b3);
        }
    }

    int r0 = rowBase + 16 * w + (lane >> 2);
    int cb = (lane & 3) * 2;
#pragma unroll
    for (int nt = 0; nt < NT; nt++) {
        int c = nt * 8 + cb;
        float v00 = acc[nt][0], v01 = acc[nt][1], v10 = acc[nt][2], v11 = acc[nt][3];
        if (bias) {
            float bc0 = bias[c], bc1 = bias[c + 1];
            v00 += bc0; v01 += bc1; v10 += bc0; v11 += bc1;
        }
        if (ACT) {
            v00 = fmaxf(v00, 0.f); v01 = fmaxf(v01, 0.f);
            v10 = fmaxf(v10, 0.f); v11 = fmaxf(v11, 0.f);
        }
        void* op = outA;
        int col = c, ld = ldA;
        if (NOUT == 128 && c >= 64) { op = outB; col = c - 64; ld = ldB; }
        if (HOUT) {
            __half* o = (__half*)op;
            if (r0 < n) {
                __half2 h = __floats2half2_rn(v00, v01);
                *(__half2*)&o[(long)r0 * ld + col] = h;
            }
            if (r0 + 8 < n) {
                __half2 h = __floats2half2_rn(v10, v11);
                *(__half2*)&o[(long)(r0 + 8) * ld + col] = h;
            }
        } else {
            float* o = (float*)op;
            if (r0 < n)     *(float2*)&o[(long)r0 * ld + col] = make_float2(v00, v01);
            if (r0 + 8 < n) *(float2*)&o[(long)(r0 + 8) * ld + col] = make_float2(v10, v11);
        }
    }
}

// ---------------- fused global add pool + post + readout + log_softmax ----------------
__global__ void poolhead_k(const void* __restrict__ batch,
                           const float* __restrict__ postW, const float* __restrict__ postb,
                           const float* __restrict__ roW, const float* __restrict__ rob,
                           float* __restrict__ out) {
    int g = blockIdx.x;
    int t = threadIdx.x;
    int lo = 0, hi = NN;
    while (lo < hi) { int mid = (lo + hi) >> 1; if (ld_idx(batch, mid) < g) lo = mid + 1; else hi = mid; }
    int beg = lo;
    hi = NN;
    while (lo < hi) { int mid = (lo + hi) >> 1; if (ld_idx(batch, mid) < g + 1) lo = mid + 1; else hi = mid; }
    int end = lo;

    float acc = 0.f;
    for (int nd = beg; nd < end; nd++) acc += g_x2[(long)nd * 64 + t];

    __shared__ float sg[64], sh1[64], sl[10];
    sg[t] = acc;
    __syncthreads();
    float a = postb[t];
#pragma unroll
    for (int k = 0; k < 64; k++) a = fmaf(sg[k], postW[k * 64 + t], a);
    sh1[t] = fmaxf(a, 0.f);
    __syncthreads();
    if (t < 10) {
        float r = rob[t];
#pragma unroll
        for (int k = 0; k < 64; k++) r = fmaf(sh1[k], roW[k * 10 + t], r);
        sl[t] = r;
    }
    __syncthreads();
    if (t == 0) {
        float m = sl[0];
#pragma unroll
        for (int c = 1; c < 10; c++) m = fmaxf(m, sl[c]);
        float sum = 0.f;
#pragma unroll
        for (int c = 0; c < 10; c++) sum += expf(sl[c] - m);
        float lse = m + logf(sum);
#pragma unroll
        for (int c = 0; c < 10; c++) out[g * 10 + c] = sl[c] - lse;
    }
}

// ---------------- launch ----------------
extern "C" void kernel_launch(void* const* d_in, const int* in_sizes, int n_in,
                              void* d_out, int out_size) {
    const float* x_in  = (const float*)d_in[0];
    const float* s_in  = (const float*)d_in[1];
    const void*  ei    = d_in[2];
    const void*  batch = d_in[3];
    const float* preW  = (const float*)d_in[4];
    const float* preb  = (const float*)d_in[5];
    const float* embW  = (const float*)d_in[6];
    const float* embb  = (const float*)d_in[7];
    const float* ginW1 = (const float*)d_in[8];
    const float* ginb1 = (const float*)d_in[9];
    const float* ginW2 = (const float*)d_in[10];
    const float* ginb2 = (const float*)d_in[11];
    const float* gcnW  = (const float*)d_in[12];
    const float* gcnb  = (const float*)d_in[13];
    const float* whpW  = (const float*)d_in[14];
    const float* whpb  = (const float*)d_in[15];
    const float* postW = (const float*)d_in[16];
    const float* postb = (const float*)d_in[17];
    const float* roW   = (const float*)d_in[18];
    const float* rob   = (const float*)d_in[19];
    float* out = (float*)d_out;

    void *p_degi, *p_cnt, *p_xc, *p_y16, *p_hs16, *p_z16, *p_x2, *p_w16;
    cudaGetSymbolAddress(&p_degi, g_degi);
    cudaGetSymbolAddress(&p_cnt, g_cnt);
    cudaGetSymbolAddress(&p_xc, g_xc);
    cudaGetSymbolAddress(&p_y16, g_y16);
    cudaGetSymbolAddress(&p_hs16, g_hs16);
    cudaGetSymbolAddress(&p_z16, g_z16);
    cudaGetSymbolAddress(&p_x2, g_x2);
    cudaGetSymbolAddress(&p_w16, g_w16);
    __half* xc16 = (__half*)p_xc;
    __half* w16 = (__half*)p_w16;

    // one-time resources (host-side objects; captured GPU work is identical every call)
    static cudaStream_t sSide = nullptr;
    static cudaEvent_t evFork = nullptr, evJoin = nullptr;
    if (sSide == nullptr) {
        cudaStreamCreateWithFlags(&sSide, cudaStreamNonBlocking);
        cudaEventCreateWithFlags(&evFork, cudaEventDisableTiming);
        cudaEventCreateWithFlags(&evJoin, cudaEventDisableTiming);
    }

    const int SM128 = 192 * 136 * 2;  // 52224  (K=128, NOUT=64)
    const int SMDUAL = 256 * 136 * 2; // 69632  (K=128, NOUT=128)
    const int SM64  = 192 * 72 * 2;   // 27648  (K=64)
    const int SM16  = 192 * 24 * 2;   // 9216   (K=16)
    cudaFuncSetAttribute(hgemm_k<128, 64, 0, 1, 1>,  cudaFuncAttributeMaxDynamicSharedMemorySize, SM128);
    cudaFuncSetAttribute(hgemm_k<16, 64, 0, 1, 1>,   cudaFuncAttributeMaxDynamicSharedMemorySize, SM16);
    cudaFuncSetAttribute(hgemm_k<128, 128, 0, 1, 0>, cudaFuncAttributeMaxDynamicSharedMemorySize, SMDUAL);
    cudaFuncSetAttribute(hgemm_k<64, 64, 1, 1, 0>,   cudaFuncAttributeMaxDynamicSharedMemorySize, SM64);
    cudaFuncSetAttribute(hgemm_k<128, 64, 0, 0, 0>,  cudaFuncAttributeMaxDynamicSharedMemorySize, SM128);

    const int TB = 256;
    const int gridE = (EE + TB - 1) / TB;
    const int gridN = (NN + TB - 1) / TB;
    const int gridW = (NN * 32 + TB - 1) / TB;
    const int gridM = (NN + 127) / 128;   // 391 CTAs

    // ---- fork: CSR build on side stream, weights+prologue GEMMs on main ----
    cudaEventRecord(evFork, 0);
    cudaStreamWaitEvent(sSide, evFork, 0);

    // side branch: CSR build chain
    cudaMemsetAsync(p_degi, 0, NN * sizeof(int), sSide);
    cudaMemsetAsync(p_cnt, 0, NN * sizeof(int), sSide);
    detect_k<<<1, 32, 0, sSide>>>((const int*)ei);
    hist_k<<<gridE, TB, 0, sSide>>>(ei);
    scan1_k<<<NB1, 1024, 0, sSide>>>();
    scan2_k<<<1, 64, 0, sSide>>>();
    scan3_k<<<gridN, TB, 0, sSide>>>();
    fill_k<<<gridE, TB, 0, sSide>>>(ei);
    cudaEventRecord(evJoin, sSide);

    // main branch: weight conversion + pre/emb + first dual GEMM
    convw_k<<<(W_TOTAL + 255) / 256, 256>>>(ginW1, gcnW, ginW2, whpW, preW, embW);
    hgemm_k<128, 64, 0, 1, 1><<<gridM, 256, SM128>>>(x_in, 128, w16 + W_PRE, preb, NN,
                                                     xc16, 128, nullptr, 0);
    hgemm_k<16, 64, 0, 1, 1><<<gridM, 256, SM16>>>(s_in, 16, w16 + W_EMB, embb, NN,
                                                   xc16 + 64, 128, nullptr, 0);
    hgemm_k<128, 128, 0, 1, 0><<<gridM, 256, SMDUAL>>>(xc16, 128, w16 + W_DUAL,
                                                       nullptr, NN, p_y16, 64, p_hs16, 64);

    // join: aggregation needs the CSR
    cudaStreamWaitEvent(0, evJoin, 0);

    for (int i = 0; i < LL; i++) {
        if (i > 0)
            hgemm_k<128, 128, 0, 1, 0><<<gridM, 256, SMDUAL>>>(
                xc16, 128, w16 + W_DUAL + i * 16384, nullptr, NN, p_y16, 64, p_hs16, 64);
        agg_fused_k<<<gridW, TB>>>(ginb1 + i * 64, gcnb + i * 64);
        hgemm_k<64, 64, 1, 1, 0><<<gridM, 256, SM64>>>(p_z16, 64, w16 + W_GIN2 + i * 4096,
                                                       ginb2 + i * 64, NN, xc16, 128, nullptr, 0);
    }

    hgemm_k<128, 64, 0, 0, 0><<<gridM, 256, SM128>>>(xc16, 128, w16 + W_WHP, whpb, NN,
                                                     p_x2, 64, nullptr, 0);
    poolhead_k<<<GG, 64>>>(batch, postW, postb, roW, rob, out);
}